// round 3
// baseline (speedup 1.0000x reference)
#include <cuda_runtime.h>
#include <cstddef>

// ================= scratch (device globals; no allocations) =================
__device__ float g_F[4 * 17 * 4096];        // [b][j][m]
__device__ float g_WhT[7 * 1024 * 512];     // [u][co][ho]
__device__ float g_Vp[8 * 4 * 17 * 1024];   // [chunk][t][j][co]
__device__ float g_V[4 * 17 * 1024];        // [t][j][co]
__device__ float g_Kp[8 * 10 * 17 * 512];   // [split][rdm][j][ho]
__device__ float g_K[10 * 17 * 512];        // [rdm = r*5+dm][j][ho]
__device__ float g_fbp[16 * 512];
__device__ float g_fullbias[512];
__device__ float g_clo[4 * 1024];           // f[b,0,:]*V3 + b_up
__device__ float g_chi[4 * 1024];           // f[b,4095,:]*V0 + b_up
__device__ float g_fixp[4 * 6 * 4 * 512];
__device__ int   g_is64;

// (u,t) pairs per rdm = r*5 + (dm+2)  -- derived tap map of upsample+head
__constant__ int c_npair[10] = {2,4,4,3,1, 1,3,4,4,2};
__constant__ int c_pu[10][4] = {
  {1,0,0,0},{3,2,1,0},{5,4,3,2},{6,5,4,0},{6,0,0,0},
  {0,0,0,0},{2,1,0,0},{4,3,2,1},{6,5,4,3},{6,5,0,0}};
__constant__ int c_pt[10][4] = {
  {0,1,0,0},{0,1,2,3},{0,1,2,3},{1,2,3,0},{3,0,0,0},
  {0,0,0,0},{0,1,2,0},{0,1,2,3},{0,1,2,3},{2,3,0,0}};
// boundary columns and their spurious-term tables
__constant__ int c_nlist[6] = {0,1,2, 8189,8190,8191};
__constant__ int c_ncorr[6] = {3,2,1, 1,2,3};
__constant__ int c_fu[6][3] = {{0,1,2},{0,1,0},{0,0,0},{6,0,0},{5,6,0},{4,5,6}};
__constant__ int c_fs[6][3] = {{0,0,1},{0,1,0},{1,0,0},{2,0,0},{2,0,0},{2,0,0}}; // 0=b_up 1=clo 2=chi

// ================= kernels =================

// detect int64 vs int32 indices (values in [0,1024) or -1 -> int64 high words are 0/-1)
__global__ void k_detect(const unsigned int* w) {
    if (threadIdx.x == 0) {
        int is64 = 1;
        for (int i = 0; i < 256; ++i) {
            unsigned v = w[2 * i + 1];
            if (v != 0u && v != 0xFFFFFFFFu) { is64 = 0; break; }
        }
        g_is64 = is64;
    }
}

// F[b][j][m]: j = g*8+d residual-summed scaled codes; j=16 -> 1.0
__global__ void k_F(const void* idxraw, const float* __restrict__ cb,
                    const float* __restrict__ sc) {
    __shared__ float ssc[128];
    int tid = threadIdx.x;
    if (tid < 128) ssc[tid] = sc[tid];
    __syncthreads();
    int gt = blockIdx.x * 256 + tid;
    int b = gt >> 12, m = gt & 4095;
    int is64 = g_is64;
    float acc[16];
#pragma unroll
    for (int j = 0; j < 16; ++j) acc[j] = 0.f;
#pragma unroll
    for (int gq = 0; gq < 16; ++gq) {
        long long c;
        size_t off = (size_t)(b * 16 + gq) * 4096 + m;
        if (is64) c = ((const long long*)idxraw)[off];
        else      c = ((const int*)idxraw)[off];
        if (c >= 0) {
            const float4* row = (const float4*)(cb + ((size_t)gq * 1024 + (int)c) * 8);
            float4 r0 = row[0], r1 = row[1];
            int jb = (gq >> 3) * 8;
            const float* s = &ssc[gq * 8];
            acc[jb+0] += r0.x*s[0]; acc[jb+1] += r0.y*s[1];
            acc[jb+2] += r0.z*s[2]; acc[jb+3] += r0.w*s[3];
            acc[jb+4] += r1.x*s[4]; acc[jb+5] += r1.y*s[5];
            acc[jb+6] += r1.z*s[6]; acc[jb+7] += r1.w*s[7];
        }
    }
#pragma unroll
    for (int j = 0; j < 16; ++j) g_F[((size_t)b * 17 + j) * 4096 + m] = acc[j];
    g_F[((size_t)b * 17 + 16) * 4096 + m] = 1.0f;
}

// transpose W_head [ho][co][u] -> WhT[u][co][ho]
__global__ void k_WhT(const float* __restrict__ Wh) {
    size_t o = (size_t)blockIdx.x * 256 + threadIdx.x;
    if (o < (size_t)7 * 1024 * 512) {
        int u = (int)(o / (1024 * 512));
        int rem = (int)(o % (1024 * 512));
        int co = rem / 512, ho = rem % 512;
        g_WhT[o] = Wh[((size_t)ho * 1024 + co) * 7 + u];
    }
}

// Vp[chunk][t][j][co] = partial over c-chunk of P[j][c]*W_up[c][co][t]
__global__ void k_Vp(const float* __restrict__ W_out, const float* __restrict__ b_out,
                     const float* __restrict__ W_up) {
    __shared__ float sW[8 * 128];
    __shared__ float sBo[128];
    int tid = threadIdx.x;
    int cotile = blockIdx.x, chunk = blockIdx.y;
    int co = cotile * 128 + tid;
    int g = chunk >> 2;
    int ebase = chunk * 128 - g * 512;
    for (int i = tid; i < 1024; i += 128) {
        int d = i >> 7, e = i & 127;
        sW[i] = W_out[((size_t)g * 8 + d) * 512 + ebase + e];
    }
    sBo[tid] = b_out[g * 512 + ebase + tid];
    __syncthreads();
    float acc[4][9];
#pragma unroll
    for (int t = 0; t < 4; ++t)
#pragma unroll
        for (int jj = 0; jj < 9; ++jj) acc[t][jj] = 0.f;
    for (int i = 0; i < 128; ++i) {
        int c = chunk * 128 + i;
        float4 w = *(const float4*)&W_up[((size_t)c * 1024 + co) * 4];
        float wt[4] = {w.x, w.y, w.z, w.w};
#pragma unroll
        for (int d = 0; d < 8; ++d) {
            float p = sW[d * 128 + i];
#pragma unroll
            for (int t = 0; t < 4; ++t) acc[t][d] += p * wt[t];
        }
        float pb = sBo[i];
#pragma unroll
        for (int t = 0; t < 4; ++t) acc[t][8] += pb * wt[t];
    }
#pragma unroll
    for (int t = 0; t < 4; ++t) {
#pragma unroll
        for (int d = 0; d < 8; ++d) {
            g_Vp[(((size_t)chunk * 4 + t) * 17 + (g * 8 + d)) * 1024 + co] = acc[t][d];
            g_Vp[(((size_t)chunk * 4 + t) * 17 + ((1 - g) * 8 + d)) * 1024 + co] = 0.f;
        }
        g_Vp[(((size_t)chunk * 4 + t) * 17 + 16) * 1024 + co] = acc[t][8];
    }
}

__global__ void k_Vred() {
    int idx = blockIdx.x * 256 + threadIdx.x;
    if (idx < 4 * 17 * 1024) {
        float s = 0.f;
#pragma unroll
        for (int sp = 0; sp < 8; ++sp) s += g_Vp[(size_t)sp * (4 * 17 * 1024) + idx];
        g_V[idx] = s;
    }
}

// Kp[split][rdm][j][ho] = partial over co-chunk of sum_pairs V[t][j][co]*WhT[u][co][ho]
__global__ void k_Kp() {
    __shared__ float sV[2176];   // [4t][17j][32co]
    int tid = threadIdx.x;
    int ho = blockIdx.x * 128 + tid;
    int rdm = blockIdx.y, sp = blockIdx.z;
    float acc[17];
#pragma unroll
    for (int j = 0; j < 17; ++j) acc[j] = 0.f;
    int np = c_npair[rdm];
    for (int cb = 0; cb < 4; ++cb) {
        int co0 = sp * 128 + cb * 32;
        __syncthreads();
        for (int i = tid; i < 2176; i += 128) {
            int t = i / 544, r = i % 544, j = r / 32, cl = r & 31;
            sV[i] = g_V[((size_t)t * 17 + j) * 1024 + co0 + cl];
        }
        __syncthreads();
        for (int cl = 0; cl < 32; ++cl) {
            int co = co0 + cl;
            for (int p = 0; p < np; ++p) {
                int u = c_pu[rdm][p], t = c_pt[rdm][p];
                float wh = g_WhT[((size_t)u * 1024 + co) * 512 + ho];
#pragma unroll
                for (int j = 0; j < 17; ++j)
                    acc[j] += sV[(t * 17 + j) * 32 + cl] * wh;
            }
        }
    }
#pragma unroll
    for (int j = 0; j < 17; ++j)
        g_Kp[(((size_t)sp * 10 + rdm) * 17 + j) * 512 + ho] = acc[j];
}

// fullbias partials: sum over co-chunk of b_up[co]*sum_u WhT[u][co][ho]
__global__ void k_fbp(const float* __restrict__ b_up) {
    int sp = blockIdx.x, ho = threadIdx.x;
    float acc = 0.f;
    for (int co = sp * 64; co < sp * 64 + 64; ++co) {
        float bu = b_up[co];
#pragma unroll
        for (int u = 0; u < 7; ++u)
            acc += bu * g_WhT[((size_t)u * 1024 + co) * 512 + ho];
    }
    g_fbp[sp * 512 + ho] = acc;
}

__global__ void k_KfbRed(const float* __restrict__ b_head) {
    int bid = blockIdx.x;
    if (bid < 340) {
        int idx = bid * 256 + threadIdx.x;   // < 87040
        float s = 0.f;
#pragma unroll
        for (int sp = 0; sp < 8; ++sp) s += g_Kp[(size_t)sp * 87040 + idx];
        g_K[idx] = s;
    } else {
        int i = (bid - 340) * 256 + threadIdx.x;
        if (i < 512) {
            float s = b_head[i];
#pragma unroll
            for (int sp = 0; sp < 16; ++sp) s += g_fbp[sp * 512 + i];
            g_fullbias[i] = s;
        }
    }
}

// c_lo[b][co] = b_up + f[b,0,:]*V3 ; c_hi[b][co] = b_up + f[b,4095,:]*V0
__global__ void k_corr1(const float* __restrict__ b_up) {
    int b = blockIdx.x >> 1, hi = blockIdx.x & 1;
    int co = threadIdx.x;
    int frame = hi ? 4095 : 0;
    int t = hi ? 0 : 3;
    float acc = b_up[co];
#pragma unroll
    for (int j = 0; j < 17; ++j)
        acc += g_F[((size_t)b * 17 + j) * 4096 + frame] * g_V[((size_t)t * 17 + j) * 1024 + co];
    if (hi) g_chi[b * 1024 + co] = acc; else g_clo[b * 1024 + co] = acc;
}

// spurious-term dot products (partial over co chunks of 256)
__global__ void k_corrD(const float* __restrict__ b_up) {
    int bi = blockIdx.x; int b = bi / 6, ni = bi % 6;
    int s = blockIdx.y;
    int ho = threadIdx.x;
    float acc = 0.f;
    int nt = c_ncorr[ni];
    for (int k = 0; k < nt; ++k) {
        int u = c_fu[ni][k], src = c_fs[ni][k];
        const float* cof = (src == 0) ? b_up : (src == 1 ? g_clo + b * 1024 : g_chi + b * 1024);
        int c0 = s * 256;
        for (int c = c0; c < c0 + 256; ++c)
            acc += cof[c] * g_WhT[((size_t)u * 1024 + c) * 512 + ho];
    }
    g_fixp[(((size_t)b * 6 + ni) * 4 + s) * 512 + ho] = acc;
}

// main fused GEMM: x[b,ho,2m0+r] = sum_{dm,j} f[b,m0+dm-2,j]*K[r][dm][j][ho] + bias
__global__ void __launch_bounds__(256) k_main(float* __restrict__ out) {
    __shared__ float sA[17 * 72];        // [j][m-window 68, pad 72]
    __shared__ float sB[2 * 85 * 64];    // [r][dm*17+j][ho 64]
    int tid = threadIdx.x;
    int mb = blockIdx.x * 64;
    int hb = blockIdx.y * 64;
    int b = blockIdx.z;
#pragma unroll 4
    for (int i = tid; i < 2 * 85 * 64; i += 256) {
        int q = i >> 6, hol = i & 63;
        sB[i] = g_K[(size_t)q * 512 + hb + hol];
    }
    for (int i = tid; i < 17 * 68; i += 256) {
        int j = i / 68, x = i % 68;
        int m = mb + x - 2;
        sA[j * 72 + x] = (m >= 0 && m < 4096) ? g_F[((size_t)b * 17 + j) * 4096 + m] : 0.f;
    }
    __syncthreads();
    int tm = tid & 15, tho = tid >> 4;
    float acc[2][4][4];
#pragma unroll
    for (int r = 0; r < 2; ++r)
#pragma unroll
        for (int mi = 0; mi < 4; ++mi)
#pragma unroll
            for (int hi = 0; hi < 4; ++hi) acc[r][mi][hi] = 0.f;

    for (int j = 0; j < 17; ++j) {
        float4 wa = *(const float4*)&sA[j * 72 + tm * 4];
        float4 wb = *(const float4*)&sA[j * 72 + tm * 4 + 4];
        float w[8] = {wa.x, wa.y, wa.z, wa.w, wb.x, wb.y, wb.z, wb.w};
#pragma unroll
        for (int dm = 0; dm < 5; ++dm) {
            float4 b0 = *(const float4*)&sB[(dm * 17 + j) * 64 + tho * 4];
            float4 b1 = *(const float4*)&sB[5440 + (dm * 17 + j) * 64 + tho * 4];
            float bb0[4] = {b0.x, b0.y, b0.z, b0.w};
            float bb1[4] = {b1.x, b1.y, b1.z, b1.w};
#pragma unroll
            for (int mi = 0; mi < 4; ++mi) {
                float a = w[mi + dm];
#pragma unroll
                for (int hi = 0; hi < 4; ++hi) {
                    acc[0][mi][hi] += a * bb0[hi];
                    acc[1][mi][hi] += a * bb1[hi];
                }
            }
        }
    }
    int nb = 2 * (mb + tm * 4);
#pragma unroll
    for (int hi = 0; hi < 4; ++hi) {
        int ho = hb + tho * 4 + hi;
        float fb = g_fullbias[ho];
        float* po = out + ((size_t)b * 512 + ho) * 8192 + nb;
        float4 v0 = {acc[0][0][hi] + fb, acc[1][0][hi] + fb,
                     acc[0][1][hi] + fb, acc[1][1][hi] + fb};
        float4 v1 = {acc[0][2][hi] + fb, acc[1][2][hi] + fb,
                     acc[0][3][hi] + fb, acc[1][3][hi] + fb};
        *(float4*)po = v0;
        *(float4*)(po + 4) = v1;
    }
}

__global__ void k_fixapply(float* __restrict__ out) {
    int b = blockIdx.x / 6, ni = blockIdx.x % 6;
    int ho = threadIdx.x;
    float d = 0.f;
#pragma unroll
    for (int s = 0; s < 4; ++s) d += g_fixp[(((size_t)b * 6 + ni) * 4 + s) * 512 + ho];
    int n = c_nlist[ni];
    out[((size_t)b * 512 + ho) * 8192 + n] -= d;
}

// ================= host =================
extern "C" void kernel_launch(void* const* d_in, const int* in_sizes, int n_in,
                              void* d_out, int out_size) {
    const void*  idx    = d_in[0];
    const float* cb     = (const float*)d_in[1];
    const float* sc     = (const float*)d_in[2];
    const float* W_out  = (const float*)d_in[3];
    const float* b_out  = (const float*)d_in[4];
    const float* W_up   = (const float*)d_in[5];
    const float* b_up   = (const float*)d_in[6];
    const float* W_head = (const float*)d_in[7];
    const float* b_head = (const float*)d_in[8];
    float* out = (float*)d_out;

    k_detect<<<1, 32>>>((const unsigned int*)idx);
    k_F<<<64, 256>>>(idx, cb, sc);
    k_WhT<<<14336, 256>>>(W_head);
    k_Vp<<<dim3(8, 8), 128>>>(W_out, b_out, W_up);
    k_Vred<<<272, 256>>>();
    k_Kp<<<dim3(4, 10, 8), 128>>>();
    k_fbp<<<16, 512>>>(b_up);
    k_KfbRed<<<342, 256>>>(b_head);
    k_corr1<<<8, 1024>>>(b_up);
    k_corrD<<<dim3(24, 4), 512>>>(b_up);
    k_main<<<dim3(64, 8, 4), 256>>>(out);
    k_fixapply<<<24, 512>>>(out);
}

// round 4
// speedup vs baseline: 1.0274x; 1.0274x over previous
#include <cuda_runtime.h>
#include <cstddef>

typedef unsigned long long ull;

// ================= scratch (device globals; no allocations) =================
__device__ float g_F[4 * 17 * 4096];         // [b][j][m]
__device__ float g_WhT[7 * 1024 * 512];      // [u][co][ho]
__device__ float g_Vp[32 * 4 * 17 * 1024];   // [chunk][t][j][co]
__device__ float g_V[4 * 17 * 1024];         // [t][j][co]
__device__ float g_Kp[8 * 10 * 17 * 512];    // [split][rdm][j][ho]
__device__ float g_K[10 * 17 * 512];         // [rdm = r*5+dm][j][ho]
__device__ float g_fbp[16 * 512];
__device__ float g_fullbias[512];
__device__ float g_clo[4 * 1024];            // f[b,0,:]*V3 + b_up
__device__ float g_chi[4 * 1024];            // f[b,4095,:]*V0 + b_up
__device__ float g_fixp[4 * 6 * 4 * 512];
__device__ int   g_is64;

// (u,t) pairs per rdm = r*5 + (dm+2)  -- derived tap map of upsample+head
__constant__ int c_npair[10] = {2,4,4,3,1, 1,3,4,4,2};
__constant__ int c_pu[10][4] = {
  {1,0,0,0},{3,2,1,0},{5,4,3,2},{6,5,4,0},{6,0,0,0},
  {0,0,0,0},{2,1,0,0},{4,3,2,1},{6,5,4,3},{6,5,0,0}};
__constant__ int c_pt[10][4] = {
  {0,1,0,0},{0,1,2,3},{0,1,2,3},{1,2,3,0},{3,0,0,0},
  {0,0,0,0},{0,1,2,0},{0,1,2,3},{0,1,2,3},{2,3,0,0}};
// boundary columns and their spurious-term tables
__constant__ int c_nlist[6] = {0,1,2, 8189,8190,8191};
__constant__ int c_ncorr[6] = {3,2,1, 1,2,3};
__constant__ int c_fu[6][3] = {{0,1,2},{0,1,0},{0,0,0},{6,0,0},{5,6,0},{4,5,6}};
__constant__ int c_fs[6][3] = {{0,0,1},{0,1,0},{1,0,0},{2,0,0},{2,0,0},{2,0,0}}; // 0=b_up 1=clo 2=chi

__device__ __forceinline__ void ffma2(ull &d, const ull a, const ull b) {
    asm("fma.rn.f32x2 %0, %1, %2, %0;" : "+l"(d) : "l"(a), "l"(b));
}
__device__ __forceinline__ float2 u2f(ull v) {
    float2 r; asm("mov.b64 {%0,%1}, %2;" : "=f"(r.x), "=f"(r.y) : "l"(v)); return r;
}

// ================= kernels =================

// detect int64 vs int32 indices (values in [0,1024) or -1 -> int64 high words are 0/-1)
__global__ void k_detect(const unsigned int* w) {
    if (threadIdx.x == 0) {
        int is64 = 1;
        for (int i = 0; i < 256; ++i) {
            unsigned v = w[2 * i + 1];
            if (v != 0u && v != 0xFFFFFFFFu) { is64 = 0; break; }
        }
        g_is64 = is64;
    }
}

// F[b][j][m]: j = g*8+d residual-summed scaled codes; j=16 -> 1.0
// one thread per (b, g, m): 32768 threads
__global__ void k_F(const void* idxraw, const float* __restrict__ cb,
                    const float* __restrict__ sc) {
    __shared__ float ssc[128];
    int tid = threadIdx.x;
    if (tid < 128) ssc[tid] = sc[tid];
    __syncthreads();
    int gt = blockIdx.x * 256 + tid;
    int m = gt & 4095, gb = (gt >> 12) & 1, b = gt >> 13;
    int is64 = g_is64;
    float acc[8];
#pragma unroll
    for (int j = 0; j < 8; ++j) acc[j] = 0.f;
#pragma unroll
    for (int qq = 0; qq < 8; ++qq) {
        int gq = gb * 8 + qq;
        size_t off = (size_t)(b * 16 + gq) * 4096 + m;
        long long c;
        if (is64) c = ((const long long*)idxraw)[off];
        else      c = ((const int*)idxraw)[off];
        if (c >= 0) {
            const float4* row = (const float4*)(cb + ((size_t)gq * 1024 + (int)c) * 8);
            float4 r0 = row[0], r1 = row[1];
            const float* s = &ssc[gq * 8];
            acc[0] += r0.x*s[0]; acc[1] += r0.y*s[1];
            acc[2] += r0.z*s[2]; acc[3] += r0.w*s[3];
            acc[4] += r1.x*s[4]; acc[5] += r1.y*s[5];
            acc[6] += r1.z*s[6]; acc[7] += r1.w*s[7];
        }
    }
#pragma unroll
    for (int j = 0; j < 8; ++j)
        g_F[((size_t)b * 17 + gb * 8 + j) * 4096 + m] = acc[j];
    if (gb == 0) g_F[((size_t)b * 17 + 16) * 4096 + m] = 1.0f;
}

// tiled transpose W_head [ho][co][u] -> WhT[u][co][ho]
__global__ void k_WhT(const float* __restrict__ Wh) {
    __shared__ float s[7][32][33];
    int tid = threadIdx.x;
    int co0 = blockIdx.x * 32, ho0 = blockIdx.y * 32;
    for (int p = tid; p < 1024; p += 256) {
        int ho_l = p >> 5, co_l = p & 31;
        const float* src = Wh + ((size_t)(ho0 + ho_l) * 1024 + co0 + co_l) * 7;
#pragma unroll
        for (int u = 0; u < 7; ++u) s[u][co_l][ho_l] = src[u];
    }
    __syncthreads();
    for (int p = tid; p < 7168; p += 256) {
        int u = p >> 10, r = p & 1023, co_l = r >> 5, ho_l = r & 31;
        g_WhT[((size_t)u * 1024 + co0 + co_l) * 512 + ho0 + ho_l] = s[u][co_l][ho_l];
    }
}

// Vp[chunk][t][j][co] = partial over 32-wide c-chunk of P[j][c]*W_up[c][co][t]
// grid (cotile 8, chunk 32) x 128 threads
__global__ void k_Vp(const float* __restrict__ W_out, const float* __restrict__ b_out,
                     const float* __restrict__ W_up) {
    __shared__ float sP[9][32];
    int tid = threadIdx.x;
    int co = blockIdx.x * 128 + tid;
    int chunk = blockIdx.y;
    int g = chunk >> 4;
    int ebase = chunk * 32 - g * 512;
    for (int i = tid; i < 288; i += 128) {
        if (i < 256) {
            int d = i >> 5, ii = i & 31;
            sP[d][ii] = W_out[((size_t)(g * 8 + d)) * 512 + ebase + ii];
        } else {
            sP[8][i - 256] = b_out[g * 512 + ebase + (i - 256)];
        }
    }
    __syncthreads();
    float acc[4][9];
#pragma unroll
    for (int t = 0; t < 4; ++t)
#pragma unroll
        for (int d = 0; d < 9; ++d) acc[t][d] = 0.f;
#pragma unroll 4
    for (int i = 0; i < 32; ++i) {
        int c = chunk * 32 + i;
        float4 w = *(const float4*)&W_up[((size_t)c * 1024 + co) * 4];
        float wt[4] = {w.x, w.y, w.z, w.w};
#pragma unroll
        for (int d = 0; d < 8; ++d) {
            float p = sP[d][i];
#pragma unroll
            for (int t = 0; t < 4; ++t) acc[t][d] += p * wt[t];
        }
        float pb = sP[8][i];
#pragma unroll
        for (int t = 0; t < 4; ++t) acc[t][8] += pb * wt[t];
    }
#pragma unroll
    for (int t = 0; t < 4; ++t) {
#pragma unroll
        for (int d = 0; d < 8; ++d) {
            g_Vp[(((size_t)chunk * 4 + t) * 17 + (g * 8 + d)) * 1024 + co] = acc[t][d];
            g_Vp[(((size_t)chunk * 4 + t) * 17 + ((1 - g) * 8 + d)) * 1024 + co] = 0.f;
        }
        g_Vp[(((size_t)chunk * 4 + t) * 17 + 16) * 1024 + co] = acc[t][8];
    }
}

__global__ void k_Vred() {
    int idx = blockIdx.x * 256 + threadIdx.x;
    if (idx < 4 * 17 * 1024) {
        float s = 0.f;
#pragma unroll
        for (int sp = 0; sp < 32; ++sp) s += g_Vp[(size_t)sp * (4 * 17 * 1024) + idx];
        g_V[idx] = s;
    }
}

// Kp[split][rdm][j][ho] = partial over co-chunk of sum_pairs V[t][j][co]*WhT[u][co][ho]
__global__ void k_Kp() {
    __shared__ float sV[2176];   // [4t][17j][32co]
    int tid = threadIdx.x;
    int ho = blockIdx.x * 128 + tid;
    int rdm = blockIdx.y, sp = blockIdx.z;
    float acc[17];
#pragma unroll
    for (int j = 0; j < 17; ++j) acc[j] = 0.f;
    int np = c_npair[rdm];
    for (int cb = 0; cb < 4; ++cb) {
        int co0 = sp * 128 + cb * 32;
        __syncthreads();
        for (int i = tid; i < 2176; i += 128) {
            int t = i / 544, r = i % 544, j = r / 32, cl = r & 31;
            sV[i] = g_V[((size_t)t * 17 + j) * 1024 + co0 + cl];
        }
        __syncthreads();
        for (int cl = 0; cl < 32; ++cl) {
            int co = co0 + cl;
            for (int p = 0; p < np; ++p) {
                int u = c_pu[rdm][p], t = c_pt[rdm][p];
                float wh = g_WhT[((size_t)u * 1024 + co) * 512 + ho];
#pragma unroll
                for (int j = 0; j < 17; ++j)
                    acc[j] += sV[(t * 17 + j) * 32 + cl] * wh;
            }
        }
    }
#pragma unroll
    for (int j = 0; j < 17; ++j)
        g_Kp[(((size_t)sp * 10 + rdm) * 17 + j) * 512 + ho] = acc[j];
}

// fullbias partials: sum over co-chunk of b_up[co]*sum_u WhT[u][co][ho]
__global__ void k_fbp(const float* __restrict__ b_up) {
    int sp = blockIdx.x, ho = threadIdx.x;
    float acc = 0.f;
    for (int co = sp * 64; co < sp * 64 + 64; ++co) {
        float bu = b_up[co];
#pragma unroll
        for (int u = 0; u < 7; ++u)
            acc += bu * g_WhT[((size_t)u * 1024 + co) * 512 + ho];
    }
    g_fbp[sp * 512 + ho] = acc;
}

__global__ void k_KfbRed(const float* __restrict__ b_head) {
    int bid = blockIdx.x;
    if (bid < 340) {
        int idx = bid * 256 + threadIdx.x;   // < 87040
        float s = 0.f;
#pragma unroll
        for (int sp = 0; sp < 8; ++sp) s += g_Kp[(size_t)sp * 87040 + idx];
        g_K[idx] = s;
    } else {
        int i = (bid - 340) * 256 + threadIdx.x;
        if (i < 512) {
            float s = b_head[i];
#pragma unroll
            for (int sp = 0; sp < 16; ++sp) s += g_fbp[sp * 512 + i];
            g_fullbias[i] = s;
        }
    }
}

// c_lo[b][co] = b_up + f[b,0,:]*V3 ; c_hi[b][co] = b_up + f[b,4095,:]*V0
__global__ void k_corr1(const float* __restrict__ b_up) {
    int b = blockIdx.x >> 1, hi = blockIdx.x & 1;
    int co = threadIdx.x;
    int frame = hi ? 4095 : 0;
    int t = hi ? 0 : 3;
    float acc = b_up[co];
#pragma unroll
    for (int j = 0; j < 17; ++j)
        acc += g_F[((size_t)b * 17 + j) * 4096 + frame] * g_V[((size_t)t * 17 + j) * 1024 + co];
    if (hi) g_chi[b * 1024 + co] = acc; else g_clo[b * 1024 + co] = acc;
}

// spurious-term dot products (partial over co chunks of 256)
__global__ void k_corrD(const float* __restrict__ b_up) {
    int bi = blockIdx.x; int b = bi / 6, ni = bi % 6;
    int s = blockIdx.y;
    int ho = threadIdx.x;
    float acc = 0.f;
    int nt = c_ncorr[ni];
    for (int k = 0; k < nt; ++k) {
        int u = c_fu[ni][k], src = c_fs[ni][k];
        const float* cof = (src == 0) ? b_up : (src == 1 ? g_clo + b * 1024 : g_chi + b * 1024);
        int c0 = s * 256;
        for (int c = c0; c < c0 + 256; ++c)
            acc += cof[c] * g_WhT[((size_t)u * 1024 + c) * 512 + ho];
    }
    g_fixp[(((size_t)b * 6 + ni) * 4 + s) * 512 + ho] = acc;
}

// main fused GEMM with packed f32x2 FFMA:
// x[b,ho,2m0+r] = sum_{dm,j} f[b,m0+dm-2,j]*K[r][dm][j][ho] + bias
// block tile: 64 m x 64 ho, 256 threads: tm = tid>>5 (8 m each), tho = tid&31 (2 ho packed)
__global__ void __launch_bounds__(256) k_main(float* __restrict__ out) {
    __shared__ __align__(16) float2 sA2[17 * 8 * 12];   // [j][tm][k] duplicated {a,a}
    __shared__ __align__(16) float  sB[2 * 85 * 64];    // [r*85 + dm*17 + j][ho 64]
    int tid = threadIdx.x;
    int mb = blockIdx.x * 64;
    int hb = blockIdx.y * 64;
    int b = blockIdx.z;
#pragma unroll 4
    for (int i = tid; i < 2 * 85 * 64; i += 256) {
        int q = i >> 6, hol = i & 63;
        sB[i] = g_K[(size_t)q * 512 + hb + hol];
    }
    for (int i = tid; i < 17 * 96; i += 256) {
        int j = i / 96, r = i % 96, tmw = r / 12, k = r % 12;
        int m = mb + tmw * 8 + k - 2;
        float v = (m >= 0 && m < 4096) ? g_F[((size_t)b * 17 + j) * 4096 + m] : 0.f;
        sA2[i] = make_float2(v, v);
    }
    __syncthreads();

    int tho = tid & 31, tm = tid >> 5;
    ull acc[2][8];
#pragma unroll
    for (int r = 0; r < 2; ++r)
#pragma unroll
        for (int mi = 0; mi < 8; ++mi) acc[r][mi] = 0ull;

    const ull* uA = ((const ull*)sA2) + (size_t)tm * 12;
    const ull* uB = (const ull*)sB;

    for (int j = 0; j < 17; ++j) {
        ull a[12];
#pragma unroll
        for (int k = 0; k < 12; ++k) a[k] = uA[j * 96 + k];
#pragma unroll
        for (int dm = 0; dm < 5; ++dm) {
            ull b0 = uB[(dm * 17 + j) * 32 + tho];
            ull b1 = uB[(85 + dm * 17 + j) * 32 + tho];
#pragma unroll
            for (int mi = 0; mi < 8; ++mi) {
                ffma2(acc[0][mi], a[mi + dm], b0);
                ffma2(acc[1][mi], a[mi + dm], b1);
            }
        }
    }

    int ho0 = hb + tho * 2;
    float fb0 = g_fullbias[ho0], fb1 = g_fullbias[ho0 + 1];
    float r0[16], r1[16];
#pragma unroll
    for (int mi = 0; mi < 8; ++mi) {
        float2 x0 = u2f(acc[0][mi]);   // r=0: {ho0, ho0+1}
        float2 x1 = u2f(acc[1][mi]);   // r=1
        r0[2 * mi]     = x0.x + fb0;
        r0[2 * mi + 1] = x1.x + fb0;
        r1[2 * mi]     = x0.y + fb1;
        r1[2 * mi + 1] = x1.y + fb1;
    }
    int nb = 2 * (mb + tm * 8);
    float* p0 = out + ((size_t)b * 512 + ho0) * 8192 + nb;
    float* p1 = p0 + 8192;
#pragma unroll
    for (int s = 0; s < 4; ++s) {
        *(float4*)(p0 + 4 * s) = *(float4*)&r0[4 * s];
        *(float4*)(p1 + 4 * s) = *(float4*)&r1[4 * s];
    }
}

__global__ void k_fixapply(float* __restrict__ out) {
    int b = blockIdx.x / 6, ni = blockIdx.x % 6;
    int ho = threadIdx.x;
    float d = 0.f;
#pragma unroll
    for (int s = 0; s < 4; ++s) d += g_fixp[(((size_t)b * 6 + ni) * 4 + s) * 512 + ho];
    int n = c_nlist[ni];
    out[((size_t)b * 512 + ho) * 8192 + n] -= d;
}

// ================= host =================
extern "C" void kernel_launch(void* const* d_in, const int* in_sizes, int n_in,
                              void* d_out, int out_size) {
    const void*  idx    = d_in[0];
    const float* cb     = (const float*)d_in[1];
    const float* sc     = (const float*)d_in[2];
    const float* W_out  = (const float*)d_in[3];
    const float* b_out  = (const float*)d_in[4];
    const float* W_up   = (const float*)d_in[5];
    const float* b_up   = (const float*)d_in[6];
    const float* W_head = (const float*)d_in[7];
    const float* b_head = (const float*)d_in[8];
    float* out = (float*)d_out;

    k_detect<<<1, 32>>>((const unsigned int*)idx);
    k_F<<<128, 256>>>(idx, cb, sc);
    k_WhT<<<dim3(32, 16), 256>>>(W_head);
    k_Vp<<<dim3(8, 32), 128>>>(W_out, b_out, W_up);
    k_Vred<<<272, 256>>>();
    k_Kp<<<dim3(4, 10, 8), 128>>>();
    k_fbp<<<16, 512>>>(b_up);
    k_KfbRed<<<342, 256>>>(b_head);
    k_corr1<<<8, 1024>>>(b_up);
    k_corrD<<<dim3(24, 4), 512>>>(b_up);
    k_main<<<dim3(64, 8, 4), 256>>>(out);
    k_fixapply<<<24, 512>>>(out);
}